// round 4
// baseline (speedup 1.0000x reference)
#include <cuda_runtime.h>
#include <cstdint>

// Binarize: x[4096, 8192] fp32, depth[3] -> out[4096, 3, 1024] float32,
// each output element = numeric value of the big-endian packed byte.
//
// R4: unroll grid-stride loop x2 with front-batched loads (4x LDG.128 in
// flight before any consumption) to double per-warp MLP and push DRAM
// utilization from 72% toward the ~6.3TB/s LTS cap.

#define COLS 8192
#define BPR  (COLS / 8)     // 1024 packed bytes (output floats) per row per plane

__device__ __forceinline__ void pack3(const float4 a, const float4 b,
                                      float d0, float d1, float d2,
                                      uint32_t& m0, uint32_t& m1, uint32_t& m2)
{
    const float f[8] = { a.x, a.y, a.z, a.w, b.x, b.y, b.z, b.w };
    m0 = 0; m1 = 0; m2 = 0;
#pragma unroll
    for (int e = 0; e < 8; e++) {
        const uint32_t w = 1u << (7 - e);
        m0 |= (f[e] > d0) ? w : 0u;
        m1 |= (f[e] > d1) ? w : 0u;
        m2 |= (f[e] > d2) ? w : 0u;
    }
}

__global__ __launch_bounds__(256) void binarize_kernel(
    const float* __restrict__ x,
    const float* __restrict__ depth,
    float* __restrict__ out,
    int nchunks)            // total 8-element chunks = n/8 (even)
{
    const float d0 = __ldg(depth + 0);
    const float d1 = __ldg(depth + 1);
    const float d2 = __ldg(depth + 2);

    const float4* __restrict__ x4 = reinterpret_cast<const float4*>(x);

    const int stride = gridDim.x * blockDim.x;   // in chunks, per sub-iter
    const int start  = blockIdx.x * blockDim.x + threadIdx.x;

    // Main unrolled-x2 loop: chunks c and c+stride handled together.
    int c = start;
    for (; c + stride < nchunks; c += 2 * stride) {
        const int c2 = c + stride;
        // Front-batch 4 independent LDG.128 (MLP=4).
        const float4 a0 = __ldcs(x4 + 2 * (size_t)c);
        const float4 b0 = __ldcs(x4 + 2 * (size_t)c + 1);
        const float4 a1 = __ldcs(x4 + 2 * (size_t)c2);
        const float4 b1 = __ldcs(x4 + 2 * (size_t)c2 + 1);

        uint32_t m0, m1, m2, n0, n1, n2;
        pack3(a0, b0, d0, d1, d2, m0, m1, m2);
        pack3(a1, b1, d0, d1, d2, n0, n1, n2);

        {
            const int row = c >> 10;
            const int t   = c & (BPR - 1);
            float* o = out + (size_t)row * (3 * BPR) + t;
            __stcs(o,           (float)m0);
            __stcs(o + BPR,     (float)m1);
            __stcs(o + 2 * BPR, (float)m2);
        }
        {
            const int row = c2 >> 10;
            const int t   = c2 & (BPR - 1);
            float* o = out + (size_t)row * (3 * BPR) + t;
            __stcs(o,           (float)n0);
            __stcs(o + BPR,     (float)n1);
            __stcs(o + 2 * BPR, (float)n2);
        }
    }
    // Remainder (at most one chunk per thread).
    if (c < nchunks) {
        const float4 a = __ldcs(x4 + 2 * (size_t)c);
        const float4 b = __ldcs(x4 + 2 * (size_t)c + 1);
        uint32_t m0, m1, m2;
        pack3(a, b, d0, d1, d2, m0, m1, m2);
        const int row = c >> 10;
        const int t   = c & (BPR - 1);
        float* o = out + (size_t)row * (3 * BPR) + t;
        __stcs(o,           (float)m0);
        __stcs(o + BPR,     (float)m1);
        __stcs(o + 2 * BPR, (float)m2);
    }
}

extern "C" void kernel_launch(void* const* d_in, const int* in_sizes, int n_in,
                              void* d_out, int out_size) {
    const float* x     = (const float*)d_in[0];
    const float* depth = (const float*)d_in[1];
    float*       out   = (float*)d_out;

    const int n       = in_sizes[0];   // 4096 * 8192
    const int nchunks = n / 8;

    const int block = 256;
    int grid = 148 * 8;                // persistent: up to 8 blocks/SM
    const int max_grid = (nchunks + block - 1) / block;
    if (grid > max_grid) grid = max_grid;

    binarize_kernel<<<grid, block>>>(x, depth, out, nchunks);
}

// round 5
// speedup vs baseline: 1.1231x; 1.1231x over previous
#include <cuda_runtime.h>
#include <cstdint>

// Binarize: x[4096, 8192] fp32, depth[3] -> out[4096, 3, 1024] float32,
// each output element = numeric value of the big-endian packed byte.
//
// R5: R3 structure (thread owns 8 consecutive floats; coalesced LDG.128 pair;
// 3x coalesced STG.32) + register double-buffer software pipeline: next
// iteration's loads issue BEFORE the current pack, hiding DRAM latency with
// ALU work. Single pack-code instance (R4's duplication blew up ALU).

#define COLS 8192
#define BPR  (COLS / 8)     // 1024 packed bytes (output floats) per row per plane

__global__ __launch_bounds__(256) void binarize_kernel(
    const float* __restrict__ x,
    const float* __restrict__ depth,
    float* __restrict__ out,
    int nchunks)            // total 8-element chunks = n/8
{
    const float d0 = __ldg(depth + 0);
    const float d1 = __ldg(depth + 1);
    const float d2 = __ldg(depth + 2);

    const float4* __restrict__ x4 = reinterpret_cast<const float4*>(x);

    const int stride = gridDim.x * blockDim.x;
    int c = blockIdx.x * blockDim.x + threadIdx.x;
    if (c >= nchunks) return;

    // Prologue: prefetch first chunk.
    float4 a = __ldcs(x4 + 2 * (size_t)c);
    float4 b = __ldcs(x4 + 2 * (size_t)c + 1);

#pragma unroll 1
    while (true) {
        const int cn = c + stride;
        const bool more = (cn < nchunks);

        // Issue next chunk's loads immediately (overlap with pack below).
        float4 an, bn;
        if (more) {
            an = __ldcs(x4 + 2 * (size_t)cn);
            bn = __ldcs(x4 + 2 * (size_t)cn + 1);
        }

        // Pack current chunk: big-endian bit e -> weight 1<<(7-e).
        uint32_t m0 = 0, m1 = 0, m2 = 0;
        const float f[8] = { a.x, a.y, a.z, a.w, b.x, b.y, b.z, b.w };
#pragma unroll
        for (int e = 0; e < 8; e++) {
            const uint32_t w = 1u << (7 - e);
            m0 |= (f[e] > d0) ? w : 0u;
            m1 |= (f[e] > d1) ? w : 0u;
            m2 |= (f[e] > d2) ? w : 0u;
        }

        const int row = c >> 10;           // c / BPR
        const int t   = c & (BPR - 1);
        float* o = out + (size_t)row * (3 * BPR) + t;
        __stcs(o,           (float)m0);
        __stcs(o + BPR,     (float)m1);
        __stcs(o + 2 * BPR, (float)m2);

        if (!more) break;
        a = an; b = bn; c = cn;
    }
}

extern "C" void kernel_launch(void* const* d_in, const int* in_sizes, int n_in,
                              void* d_out, int out_size) {
    const float* x     = (const float*)d_in[0];
    const float* depth = (const float*)d_in[1];
    float*       out   = (float*)d_out;

    const int n       = in_sizes[0];   // 4096 * 8192
    const int nchunks = n / 8;

    const int block = 256;
    int grid = 148 * 8;                // persistent: 8 blocks/SM
    const int max_grid = (nchunks + block - 1) / block;
    if (grid > max_grid) grid = max_grid;

    binarize_kernel<<<grid, block>>>(x, depth, out, nchunks);
}

// round 6
// speedup vs baseline: 1.2294x; 1.0947x over previous
#include <cuda_runtime.h>
#include <cstdint>

// Binarize: x[4096, 8192] fp32, depth[3] -> out[4096, 3, 1024] float32,
// each output element = numeric value of the big-endian packed byte.
//
// R6: identical to R5 except store cache hint. Output (50MB) fits in L2
// (126MB); __stcs (evict-first) was forcing dirty output lines to DRAM,
// adding ~50MB/replay of steady-state write traffic. __stcg keeps them
// L2-resident so the next graph replay overwrites them in place; input
// loads keep .cs (streaming, evict-first) so they don't displace output.

#define COLS 8192
#define BPR  (COLS / 8)     // 1024 packed bytes (output floats) per row per plane

__global__ __launch_bounds__(256) void binarize_kernel(
    const float* __restrict__ x,
    const float* __restrict__ depth,
    float* __restrict__ out,
    int nchunks)            // total 8-element chunks = n/8
{
    const float d0 = __ldg(depth + 0);
    const float d1 = __ldg(depth + 1);
    const float d2 = __ldg(depth + 2);

    const float4* __restrict__ x4 = reinterpret_cast<const float4*>(x);

    const int stride = gridDim.x * blockDim.x;
    int c = blockIdx.x * blockDim.x + threadIdx.x;
    if (c >= nchunks) return;

    // Prologue: prefetch first chunk.
    float4 a = __ldcs(x4 + 2 * (size_t)c);
    float4 b = __ldcs(x4 + 2 * (size_t)c + 1);

#pragma unroll 1
    while (true) {
        const int cn = c + stride;
        const bool more = (cn < nchunks);

        // Issue next chunk's loads immediately (overlap with pack below).
        float4 an, bn;
        if (more) {
            an = __ldcs(x4 + 2 * (size_t)cn);
            bn = __ldcs(x4 + 2 * (size_t)cn + 1);
        }

        // Pack current chunk: big-endian bit e -> weight 1<<(7-e).
        uint32_t m0 = 0, m1 = 0, m2 = 0;
        const float f[8] = { a.x, a.y, a.z, a.w, b.x, b.y, b.z, b.w };
#pragma unroll
        for (int e = 0; e < 8; e++) {
            const uint32_t w = 1u << (7 - e);
            m0 |= (f[e] > d0) ? w : 0u;
            m1 |= (f[e] > d1) ? w : 0u;
            m2 |= (f[e] > d2) ? w : 0u;
        }

        const int row = c >> 10;           // c / BPR
        const int t   = c & (BPR - 1);
        float* o = out + (size_t)row * (3 * BPR) + t;
        __stcg(o,           (float)m0);
        __stcg(o + BPR,     (float)m1);
        __stcg(o + 2 * BPR, (float)m2);

        if (!more) break;
        a = an; b = bn; c = cn;
    }
}

extern "C" void kernel_launch(void* const* d_in, const int* in_sizes, int n_in,
                              void* d_out, int out_size) {
    const float* x     = (const float*)d_in[0];
    const float* depth = (const float*)d_in[1];
    float*       out   = (float*)d_out;

    const int n       = in_sizes[0];   // 4096 * 8192
    const int nchunks = n / 8;

    const int block = 256;
    int grid = 148 * 8;                // persistent: 8 blocks/SM
    const int max_grid = (nchunks + block - 1) / block;
    if (grid > max_grid) grid = max_grid;

    binarize_kernel<<<grid, block>>>(x, depth, out, nchunks);
}

// round 7
// speedup vs baseline: 1.2912x; 1.0503x over previous
#include <cuda_runtime.h>
#include <cstdint>

// Binarize: x[4096, 8192] fp32, depth[3] -> out[4096, 3, 1024] float32,
// each output element = numeric value of the big-endian packed byte.
//
// R7: pack via direct float accumulation (if f>d: acc += 2^(7-e)) instead of
// integer mask OR + I2F. Moves per-element work from the congested alu pipe
// (55%) to the idle fma pipe (8%) and deletes the 3 I2F conversions.
// Sums of distinct powers of two <=255 are exact in fp32. Keeps R6's
// structure: 8 consecutive floats/thread, ldcs reads, stcg writes (output
// stays L2-resident across graph replays), register double-buffer pipeline.

#define COLS 8192
#define BPR  (COLS / 8)     // 1024 packed bytes (output floats) per row per plane

__global__ __launch_bounds__(256) void binarize_kernel(
    const float* __restrict__ x,
    const float* __restrict__ depth,
    float* __restrict__ out,
    int nchunks)            // total 8-element chunks = n/8
{
    const float d0 = __ldg(depth + 0);
    const float d1 = __ldg(depth + 1);
    const float d2 = __ldg(depth + 2);

    const float4* __restrict__ x4 = reinterpret_cast<const float4*>(x);

    const int stride = gridDim.x * blockDim.x;
    int c = blockIdx.x * blockDim.x + threadIdx.x;
    if (c >= nchunks) return;

    // Prologue: prefetch first chunk.
    float4 a = __ldcs(x4 + 2 * (size_t)c);
    float4 b = __ldcs(x4 + 2 * (size_t)c + 1);

#pragma unroll 1
    while (true) {
        const int cn = c + stride;
        const bool more = (cn < nchunks);

        // Issue next chunk's loads immediately (overlap with pack below).
        float4 an, bn;
        if (more) {
            an = __ldcs(x4 + 2 * (size_t)cn);
            bn = __ldcs(x4 + 2 * (size_t)cn + 1);
        }

        // Pack current chunk via float accumulation (fma pipe).
        // Big-endian: element e has weight 2^(7-e).
        const float f[8] = { a.x, a.y, a.z, a.w, b.x, b.y, b.z, b.w };
        float a0 = 0.0f, a1 = 0.0f, a2 = 0.0f;
#pragma unroll
        for (int e = 0; e < 8; e++) {
            const float w = (float)(1u << (7 - e));   // compile-time constant
            if (f[e] > d0) a0 += w;
            if (f[e] > d1) a1 += w;
            if (f[e] > d2) a2 += w;
        }

        const int row = c >> 10;           // c / BPR
        const int t   = c & (BPR - 1);
        float* o = out + (size_t)row * (3 * BPR) + t;
        __stcg(o,           a0);
        __stcg(o + BPR,     a1);
        __stcg(o + 2 * BPR, a2);

        if (!more) break;
        a = an; b = bn; c = cn;
    }
}

extern "C" void kernel_launch(void* const* d_in, const int* in_sizes, int n_in,
                              void* d_out, int out_size) {
    const float* x     = (const float*)d_in[0];
    const float* depth = (const float*)d_in[1];
    float*       out   = (float*)d_out;

    const int n       = in_sizes[0];   // 4096 * 8192
    const int nchunks = n / 8;

    const int block = 256;
    int grid = 148 * 8;                // persistent: 8 blocks/SM
    const int max_grid = (nchunks + block - 1) / block;
    if (grid > max_grid) grid = max_grid;

    binarize_kernel<<<grid, block>>>(x, depth, out, nchunks);
}